// round 6
// baseline (speedup 1.0000x reference)
#include <cuda_runtime.h>
#include <cuda_bf16.h>

#define NB     65536
#define TILE   32               // batches per tile
#define NTILE  (NB / TILE)      // 2048 tiles
#define GRID   148              // persistent: 1 block per SM
#define TPB    256              // 8 warps
#define F4ARR  (TILE * 75)      // 2400 float4 per array per tile (32 x 300 floats)
#define F4TILE (2 * F4ARR)      // A + Y
#define SCRATCHF (8 * TILE * 9) // per-warp partials: 8 warps x 32 batches x 9
#define SMEM_BYTES (2 * F4TILE * 16 + SCRATCHF * 4)

__device__ float        g_partials[GRID];
__device__ unsigned int g_counter = 0;

// clip(log(p), -100, None) -- matches reference _bce clamping.
__device__ __forceinline__ float clogf_(float x) {
    return fmaxf(__logf(x), -100.0f);
}
__device__ __forceinline__ float bce1(float p, float y) {
    return -(y * clogf_(p) + (1.0f - y) * clogf_(1.0f - p));
}

__device__ __forceinline__ void cp16(void* dst_smem, const void* src_gmem) {
    unsigned s = (unsigned)__cvta_generic_to_shared(dst_smem);
    asm volatile("cp.async.cg.shared.global [%0], [%1], 16;" :: "r"(s), "l"(src_gmem) : "memory");
}

// Stage one tile (A slice + Y slice, both contiguous in GMEM) into smem buffer.
__device__ __forceinline__ void stage_tile(float4* dst, const float4* gA, const float4* gY, int tid) {
    #pragma unroll
    for (int i = 0; i < (F4ARR + TPB - 1) / TPB; ++i) {   // 10 iters (2400 = 9*256 + 96)
        int idx = i * TPB + tid;
        if (idx < F4ARR) {
            cp16(dst + idx,         gA + idx);
            cp16(dst + F4ARR + idx, gY + idx);
        }
    }
    asm volatile("cp.async.commit_group;" ::: "memory");
}

extern __shared__ float4 smem[];   // [buf0: A(2400) Y(2400)] [buf1: ...] [scratch floats]

__global__ void __launch_bounds__(TPB, 1)
loss_kernel(const float* __restrict__ A, const float* __restrict__ CAT,
            const float* __restrict__ Y, const float* __restrict__ CATL,
            float* __restrict__ out)
{
    const int tid  = threadIdx.x;
    const int w    = tid >> 5;
    const int lane = tid & 31;

    float* scratch = reinterpret_cast<float*>(smem + 2 * F4TILE);

    const float4* gA = reinterpret_cast<const float4*>(A);
    const float4* gY = reinterpret_cast<const float4*>(Y);

    float vsum = 0.0f;

    // Prefetch first tile into buffer 0.
    const int tile0 = blockIdx.x;
    if (tile0 < NTILE)
        stage_tile(smem, gA + (size_t)tile0 * F4ARR, gY + (size_t)tile0 * F4ARR, tid);

    int bufi = 0;
    for (int tile = tile0; tile < NTILE; tile += GRID) {
        const int nxt = tile + GRID;
        if (nxt < NTILE) {
            stage_tile(smem + (bufi ^ 1) * F4TILE,
                       gA + (size_t)nxt * F4ARR, gY + (size_t)nxt * F4ARR, tid);
            asm volatile("cp.async.wait_group 1;" ::: "memory");
        } else {
            asm volatile("cp.async.wait_group 0;" ::: "memory");
        }
        __syncthreads();                              // tile data visible to all warps

        // ---- main partials: lane = batch within tile, warp = K-slice (c = w, w+8, w+16[, 24]) ----
        const float4* a4 = smem + bufi * F4TILE + lane * 75;
        const float4* y4 = a4 + F4ARR;

        float acc[3][3] = {{0.f,0.f,0.f},{0.f,0.f,0.f},{0.f,0.f,0.f}};
        float slog[3]   = {0.f, 0.f, 0.f};

        #pragma unroll 2
        for (int c = w; c < 25; c += 8) {
            float4 av[3], yv[3];
            #pragma unroll
            for (int s = 0; s < 3; ++s) av[s] = a4[s * 25 + c];
            #pragma unroll
            for (int t = 0; t < 3; ++t) yv[t] = y4[t * 25 + c];

            float4 df[3];
            #pragma unroll
            for (int s = 0; s < 3; ++s) {
                float lp, lm, sl = 0.f;
                lp = clogf_(av[s].x); lm = clogf_(1.0f - av[s].x); df[s].x = lp - lm; sl += lm;
                lp = clogf_(av[s].y); lm = clogf_(1.0f - av[s].y); df[s].y = lp - lm; sl += lm;
                lp = clogf_(av[s].z); lm = clogf_(1.0f - av[s].z); df[s].z = lp - lm; sl += lm;
                lp = clogf_(av[s].w); lm = clogf_(1.0f - av[s].w); df[s].w = lp - lm; sl += lm;
                slog[s] += sl;
            }
            #pragma unroll
            for (int s = 0; s < 3; ++s) {
                #pragma unroll
                for (int t = 0; t < 3; ++t) {
                    float a0 = acc[s][t];
                    a0 = fmaf(yv[t].x, df[s].x, a0);
                    a0 = fmaf(yv[t].y, df[s].y, a0);
                    a0 = fmaf(yv[t].z, df[s].z, a0);
                    a0 = fmaf(yv[t].w, df[s].w, a0);
                    acc[s][t] = a0;
                }
            }
        }

        // Fold slog into acc (C[s][t] needs slog[s] added to every t) and publish 9 partials.
        {
            float* my = scratch + (w * TILE + lane) * 9;
            #pragma unroll
            for (int s = 0; s < 3; ++s)
                #pragma unroll
                for (int t = 0; t < 3; ++t)
                    my[s * 3 + t] = acc[s][t] + slog[s];
        }
        __syncthreads();                              // partials visible

        // ---- epilogue: batch bl = w + 8*lane handled by one lane (lanes 0..3 of each warp) ----
        if (lane < 4) {
            const int bl = w + 8 * lane;
            float C[3][3];
            #pragma unroll
            for (int k = 0; k < 9; ++k) {
                float s_ = 0.f;
                #pragma unroll
                for (int wk = 0; wk < 8; ++wk)
                    s_ += scratch[(wk * TILE + bl) * 9 + k];
                C[k / 3][k % 3] = -s_;
            }

            // 6 permutations (itertools order); strict < keeps first-min (argmin semantics).
            float best = C[0][0] + C[1][1] + C[2][2];
            int p0 = 0, p1 = 1, p2 = 2;
            float L;
            L = C[0][0] + C[2][1] + C[1][2]; if (L < best) { best = L; p0 = 0; p1 = 2; p2 = 1; }
            L = C[1][0] + C[0][1] + C[2][2]; if (L < best) { best = L; p0 = 1; p1 = 0; p2 = 2; }
            L = C[1][0] + C[2][1] + C[0][2]; if (L < best) { best = L; p0 = 1; p1 = 2; p2 = 0; }
            L = C[2][0] + C[0][1] + C[1][2]; if (L < best) { best = L; p0 = 2; p1 = 0; p2 = 1; }
            L = C[2][0] + C[1][1] + C[0][2]; if (L < best) { best = L; p0 = 2; p1 = 1; p2 = 0; }

            const int gb = tile * TILE + bl;
            float c0 = CAT[3 * gb + 0], c1 = CAT[3 * gb + 1], c2 = CAT[3 * gb + 2];
            float l0 = CATL[3 * gb + 0], l1 = CATL[3 * gb + 1], l2 = CATL[3 * gb + 2];
            float q0 = (p0 == 0) ? c0 : ((p0 == 1) ? c1 : c2);
            float q1 = (p1 == 0) ? c0 : ((p1 == 1) ? c1 : c2);
            float q2 = (p2 == 0) ? c0 : ((p2 == 1) ? c1 : c2);
            float catsum = bce1(q0, l0) + bce1(q1, l1) + bce1(q2, l2);

            vsum += best * (1.0f / 300.0f) * (1.0f / (float)NB)
                  + catsum * (1.0f / (3.0f * (float)NB));
        }
        // Scratch re-write in next tile happens after that tile's first __syncthreads -> safe.

        bufi ^= 1;
    }

    // ---- deterministic block reduction of vsum (reuse scratch) ----
    __syncthreads();
    scratch[tid] = vsum;
    __syncthreads();
    #pragma unroll
    for (int off = TPB / 2; off > 0; off >>= 1) {
        if (tid < off) scratch[tid] += scratch[tid + off];
        __syncthreads();
    }

    __shared__ unsigned sticket;
    if (tid == 0) {
        g_partials[blockIdx.x] = scratch[0];
        __threadfence();
        sticket = atomicAdd(&g_counter, 1u);
    }
    __syncthreads();

    // Last block to finish sums the 148 partials in fixed order (deterministic) and resets.
    if (sticket == GRID - 1) {
        if (tid == 0) {
            float v = 0.f;
            #pragma unroll 4
            for (int i = 0; i < GRID; ++i) v += g_partials[i];
            out[0] = v;
            g_counter = 0;                 // self-reset for graph replays
        }
    }
}

extern "C" void kernel_launch(void* const* d_in, const int* in_sizes, int n_in,
                              void* d_out, int out_size)
{
    const float* A    = (const float*)d_in[0]; // assignments        (B,3,10,10)
    const float* CAT  = (const float*)d_in[1]; // category           (B,3)
    const float* Y    = (const float*)d_in[2]; // assignments_labels (B,3,10,10)
    const float* CATL = (const float*)d_in[3]; // category_labels    (B,3)

    cudaFuncSetAttribute(loss_kernel, cudaFuncAttributeMaxDynamicSharedMemorySize, SMEM_BYTES);
    loss_kernel<<<GRID, TPB, SMEM_BYTES>>>(A, CAT, Y, CATL, (float*)d_out);
}